// round 7
// baseline (speedup 1.0000x reference)
#include <cuda_runtime.h>
#include <cstdint>
#include <math.h>

#define BB 64
#define SS 256
#define DD 512

// ---------------- scratch (__device__ globals; no allocation) ---------------
__device__ float g_A  [BB * SS * SS];    // A[b][i][j]   (tf32-rounded)
__device__ float g_At [BB * SS * SS];    // A[b][j][i]   (tf32-rounded)
__device__ float g_F0a[BB * SS * DD];
__device__ float g_F1a[BB * SS * DD];
__device__ float g_W0t[DD * SS];         // W0^T [d][k]  (tf32-rounded)
__device__ float g_W1t[DD * SS];
__device__ float g_sq0[BB * SS];
__device__ float g_sq1[BB * SS];

// ---------------- helpers ---------------------------------------------------
__device__ __forceinline__ uint32_t smem_u32(const void* p) {
    uint32_t a;
    asm("{ .reg .u64 t; cvta.to.shared.u64 t, %1; cvt.u32.u64 %0, t; }" : "=r"(a) : "l"(p));
    return a;
}
__device__ __forceinline__ float rtf32(float x) {   // round-to-nearest tf32
    uint32_t u;
    asm("cvt.rna.tf32.f32 %0, %1;" : "=r"(u) : "f"(x));
    return __uint_as_float(u);
}
__device__ __forceinline__ uint32_t lds32(uint32_t a) {
    uint32_t v;
    asm volatile("ld.shared.b32 %0, [%1];" : "=r"(v) : "r"(a));
    return v;
}
#define CP_ASYNC16(dst, src) \
    asm volatile("cp.async.cg.shared.global [%0], [%1], 16;" :: "r"(dst), "l"(src))
#define CP_COMMIT() asm volatile("cp.async.commit_group;" ::: "memory")
#define CP_WAIT1()  asm volatile("cp.async.wait_group 1;" ::: "memory")

__device__ __forceinline__ void mma_tf32(float* c, const uint32_t* a, const uint32_t* b) {
    asm volatile(
        "mma.sync.aligned.m16n8k8.row.col.f32.tf32.tf32.f32 "
        "{%0,%1,%2,%3}, {%4,%5,%6,%7}, {%8,%9}, {%0,%1,%2,%3};"
        : "+f"(c[0]), "+f"(c[1]), "+f"(c[2]), "+f"(c[3])
        : "r"(a[0]), "r"(a[1]), "r"(a[2]), "r"(a[3]), "r"(b[0]), "r"(b[1]));
}

// ---------------------------------------------------------------------------
// Prep kernel: sqnorms (blocks 0..8191, 2 rows each) + W transpose (8192..8447)
// ---------------------------------------------------------------------------
__global__ __launch_bounds__(256) void prep_kernel(
    const float* __restrict__ F0r, const float* __restrict__ F1r,
    const float* __restrict__ m0, const float* __restrict__ m1,
    const float* __restrict__ W0, const float* __restrict__ W1)
{
    __shared__ float sh0[2][4], sh1[2][4];
    __shared__ float t[32][33];
    int bx = blockIdx.x;
    int tid = threadIdx.x;

    if (bx < 8192) {
        int half = tid >> 7, lt = tid & 127;
        int row = bx * 2 + half;
        const float4* r0 = (const float4*)(F0r + (size_t)row * DD);
        const float4* r1 = (const float4*)(F1r + (size_t)row * DD);
        float4 a = r0[lt];
        float4 b = r1[lt];
        float s0 = a.x * a.x + a.y * a.y + a.z * a.z + a.w * a.w;
        float s1 = b.x * b.x + b.y * b.y + b.z * b.z + b.w * b.w;
        #pragma unroll
        for (int o = 16; o > 0; o >>= 1) {
            s0 += __shfl_xor_sync(0xFFFFFFFFu, s0, o);
            s1 += __shfl_xor_sync(0xFFFFFFFFu, s1, o);
        }
        int w = lt >> 5;
        if ((lt & 31) == 0) { sh0[half][w] = s0; sh1[half][w] = s1; }
        __syncthreads();
        if (lt == 0) {
            s0 = sh0[half][0] + sh0[half][1] + sh0[half][2] + sh0[half][3];
            s1 = sh1[half][0] + sh1[half][1] + sh1[half][2] + sh1[half][3];
            g_sq0[row] = s0 * m0[row];
            g_sq1[row] = s1 * m1[row];
        }
    } else {
        int r = bx - 8192;                 // 0..255
        int sel = r >> 7;
        int d0 = (r & 15) * 32;
        int k0 = ((r >> 4) & 7) * 32;
        const float* W = sel ? W1 : W0;
        float* Wt = sel ? g_W1t : g_W0t;
        int tx = tid & 31, ty = tid >> 5;  // 32 x 8
        #pragma unroll
        for (int rr = 0; rr < 32; rr += 8)
            t[ty + rr][tx] = W[(size_t)(k0 + ty + rr) * DD + d0 + tx];
        __syncthreads();
        #pragma unroll
        for (int rr = 0; rr < 32; rr += 8)
            Wt[(size_t)(d0 + ty + rr) * SS + k0 + tx] = rtf32(t[tx][ty + rr]);
    }
}

// ---------------------------------------------------------------------------
// mma.sync tf32 GEMM core.  Block tile 128x128, 8 warps (64x32 each), BK=32.
// smem row: 32 floats + 4 pad (144 B, conflict-free: word = 36g + t4).
// 3-stage cp.async ring, ONE __syncthreads per 32-k tile, loads 2 tiles ahead.
// ---------------------------------------------------------------------------
#define ROWB 144
#define OPER_BYTES (128 * ROWB)            // 18432
#define STAGE_BYTES (2 * OPER_BYTES)       // 36864
#define NSTAGE 3
#define GEMM_SMEM (NSTAGE * STAGE_BYTES)   // 110592

template <int KTOT>
__device__ __forceinline__ void gemm_mainloop(
    const float* __restrict__ Ag, const float* __restrict__ Bg,
    uint32_t sb, int tid, float acc[4][4][4],
    uint32_t aoff, uint32_t boff)
{
    constexpr int T = KTOT / 32;

    auto load_tile = [&](int t, int s) {
        uint32_t ab = sb + s * STAGE_BYTES;
        uint32_t bb = ab + OPER_BYTES;
        int k0 = t * 32;
        #pragma unroll
        for (int i = 0; i < 4; i++) {
            int idx = tid + i * 256;             // 0..1023
            int row = idx >> 3, part = idx & 7;
            uint32_t doff = (uint32_t)(row * ROWB + part * 16);
            CP_ASYNC16(ab + doff, Ag + (size_t)row * KTOT + k0 + part * 4);
            CP_ASYNC16(bb + doff, Bg + (size_t)row * KTOT + k0 + part * 4);
        }
    };

    load_tile(0, 0); CP_COMMIT();
    load_tile(1, 1); CP_COMMIT();

    int s = 0;
    for (int t = 0; t < T; t++) {
        CP_WAIT1();           // tile t resident (t+1 may be in flight)
        __syncthreads();      // visibility; slot s+2 is reusable
        int lt = t + 2;
        int ls = s + 2; if (ls >= NSTAGE) ls -= NSTAGE;
        if (lt < T) load_tile(lt, ls);
        CP_COMMIT();

        uint32_t ab = sb + s * STAGE_BYTES + aoff;
        uint32_t bb = sb + s * STAGE_BYTES + OPER_BYTES + boff;
        #pragma unroll
        for (int ks = 0; ks < 4; ks++) {
            uint32_t af[4][4], bf[4][2];
            #pragma unroll
            for (int mf = 0; mf < 4; mf++) {
                uint32_t base = ab + mf * (16 * ROWB) + ks * 32;
                af[mf][0] = lds32(base);
                af[mf][1] = lds32(base + 8 * ROWB);
                af[mf][2] = lds32(base + 16);
                af[mf][3] = lds32(base + 8 * ROWB + 16);
            }
            #pragma unroll
            for (int nf = 0; nf < 4; nf++) {
                uint32_t base = bb + nf * (8 * ROWB) + ks * 32;
                bf[nf][0] = lds32(base);
                bf[nf][1] = lds32(base + 16);
            }
            #pragma unroll
            for (int mf = 0; mf < 4; mf++)
                #pragma unroll
                for (int nf = 0; nf < 4; nf++)
                    mma_tf32(acc[mf][nf], af[mf], bf[nf]);
        }
        if (++s >= NSTAGE) s -= NSTAGE;
    }
}

// ---------------------------------------------------------------------------
// GEMM A (attention): cross = F0 @ F1^T (K=512) -> epilogue -> g_A, g_At
// ---------------------------------------------------------------------------
__global__ __launch_bounds__(256, 2) void gemm_attn(
    const float* __restrict__ F0r, const float* __restrict__ F1r,
    const float* __restrict__ m0_, const float* __restrict__ m1_)
{
    extern __shared__ char smem[];
    const int tid = threadIdx.x;
    const int wid = tid >> 5, lane = tid & 31;
    const int g = lane >> 2, t4 = lane & 3;
    const int wm = wid & 1, wn = wid >> 1;
    const int b = blockIdx.z, mt = blockIdx.y, nt = blockIdx.x;

    uint32_t sb = smem_u32(smem);
    const float* Ag = F0r + (size_t)b * SS * DD + (size_t)mt * 128 * DD;
    const float* Bg = F1r + (size_t)b * SS * DD + (size_t)nt * 128 * DD;

    float acc[4][4][4];
    #pragma unroll
    for (int i = 0; i < 4; i++)
        #pragma unroll
        for (int j = 0; j < 4; j++)
            #pragma unroll
            for (int r = 0; r < 4; r++) acc[i][j][r] = 0.f;

    const uint32_t aoff = (uint32_t)((wm * 64 + g) * ROWB + t4 * 4);
    const uint32_t boff = (uint32_t)((wn * 32 + g) * ROWB + t4 * 4);

    gemm_mainloop<512>(Ag, Bg, sb, tid, acc, aoff, boff);

    // -------------------- attention epilogue (two 64-row halves) ------------
    float* tile = (float*)smem;                         // [64][132]
    float* s_sq0 = (float*)(smem + 33792);              // [128]
    float* s_a0  = s_sq0 + 128;
    float* s_sq1 = s_a0 + 128;
    float* s_m1  = s_sq1 + 128;

    __syncthreads();   // mainloop smem dead
    if (tid < 128) {
        int i = tid;
        s_sq0[i] = g_sq0[b * SS + mt * 128 + i];
        s_a0[i]  = 2.f * m0_[b * SS + mt * 128 + i];
        s_sq1[i] = g_sq1[b * SS + nt * 128 + i];
        s_m1[i]  = m1_[b * SS + nt * 128 + i];
    }

    float* Aout  = g_A  + (size_t)b * SS * SS;
    float* Atout = g_At + (size_t)b * SS * SS;

    #pragma unroll 1
    for (int h = 0; h < 2; h++) {
        __syncthreads();
        if (wm == h) {
            #pragma unroll
            for (int mf = 0; mf < 4; mf++) {
                int lr = mf * 16 + g;
                #pragma unroll
                for (int nf = 0; nf < 4; nf++) {
                    int col = wn * 32 + nf * 8 + 2 * t4;
                    *(float2*)&tile[lr * 132 + col] =
                        make_float2(acc[mf][nf][0], acc[mf][nf][1]);
                    *(float2*)&tile[(lr + 8) * 132 + col] =
                        make_float2(acc[mf][nf][2], acc[mf][nf][3]);
                }
            }
        }
        __syncthreads();

        #pragma unroll
        for (int it = 0; it < 8; it++) {
            int lin = it * 1024 + tid * 4;
            int row = lin >> 7, col = lin & 127;
            int grow = h * 64 + row;
            float s0v = s_sq0[grow], a0v = s_a0[grow];
            float4 cr = *(float4*)&tile[row * 132 + col];
            float d2, v0, v1, v2, v3;
            d2 = fmaxf(s0v + s_sq1[col]     - a0v * s_m1[col]     * cr.x, 0.f);
            v0 = rtf32(1.f / (1.f + sqrtf(d2)));
            d2 = fmaxf(s0v + s_sq1[col + 1] - a0v * s_m1[col + 1] * cr.y, 0.f);
            v1 = rtf32(1.f / (1.f + sqrtf(d2)));
            d2 = fmaxf(s0v + s_sq1[col + 2] - a0v * s_m1[col + 2] * cr.z, 0.f);
            v2 = rtf32(1.f / (1.f + sqrtf(d2)));
            d2 = fmaxf(s0v + s_sq1[col + 3] - a0v * s_m1[col + 3] * cr.w, 0.f);
            v3 = rtf32(1.f / (1.f + sqrtf(d2)));
            *(float4*)&Aout[(size_t)(mt * 128 + grow) * SS + nt * 128 + col] =
                make_float4(v0, v1, v2, v3);
        }

        #pragma unroll
        for (int it = 0; it < 8; it++) {
            int pair = it * 256 + tid;
            int col = pair >> 4, rg = pair & 15;
            int r0 = rg * 4;
            float s1v = s_sq1[col], m1v = s_m1[col];
            float v[4];
            #pragma unroll
            for (int q = 0; q < 4; q++) {
                int row = r0 + q, grow = h * 64 + row;
                float cr = tile[row * 132 + col];
                float d2 = fmaxf(s_sq0[grow] + s1v - s_a0[grow] * m1v * cr, 0.f);
                v[q] = rtf32(1.f / (1.f + sqrtf(d2)));
            }
            *(float4*)&Atout[(size_t)(nt * 128 + col) * SS + mt * 128 + h * 64 + r0] =
                make_float4(v[0], v[1], v[2], v[3]);
        }
    }
}

// ---------------------------------------------------------------------------
// GEMM B (both aggregations in ONE launch).  blockIdx.y: 0,1 -> F0a (At@W0t),
// 2,3 -> F1a (A@W1t).  K=256.
// ---------------------------------------------------------------------------
__global__ __launch_bounds__(256, 2) void gemm_aggr(void)
{
    extern __shared__ char smem[];
    const int tid = threadIdx.x;
    const int wid = tid >> 5, lane = tid & 31;
    const int g = lane >> 2, t4 = lane & 3;
    const int wm = wid & 1, wn = wid >> 1;
    const int b = blockIdx.z, nt = blockIdx.x;
    const int sel = blockIdx.y >> 1;          // 0: F0a, 1: F1a
    const int mt  = blockIdx.y & 1;

    uint32_t sb = smem_u32(smem);
    const float* Ag = (sel ? g_A : g_At) + (size_t)b * SS * SS + (size_t)mt * 128 * SS;
    const float* Bg = (sel ? g_W1t : g_W0t) + (size_t)nt * 128 * SS;

    float acc[4][4][4];
    #pragma unroll
    for (int i = 0; i < 4; i++)
        #pragma unroll
        for (int j = 0; j < 4; j++)
            #pragma unroll
            for (int r = 0; r < 4; r++) acc[i][j][r] = 0.f;

    const uint32_t aoff = (uint32_t)((wm * 64 + g) * ROWB + t4 * 4);
    const uint32_t boff = (uint32_t)((wn * 32 + g) * ROWB + t4 * 4);

    gemm_mainloop<256>(Ag, Bg, sb, tid, acc, aoff, boff);

    float* O = (sel ? g_F1a : g_F0a) + (size_t)b * SS * DD;
    #pragma unroll
    for (int mf = 0; mf < 4; mf++) {
        int m = mt * 128 + wm * 64 + mf * 16 + g;
        #pragma unroll
        for (int nf = 0; nf < 4; nf++) {
            int col = nt * 128 + wn * 32 + nf * 8 + 2 * t4;
            *(float2*)&O[(size_t)m * DD + col] =
                make_float2(acc[mf][nf][0], acc[mf][nf][1]);
            *(float2*)&O[(size_t)(m + 8) * DD + col] =
                make_float2(acc[mf][nf][2], acc[mf][nf][3]);
        }
    }
}

// ---------------------------------------------------------------------------
// Conv (2ch, h=3, pad 2) + bias + tanh + avgpool(3), float4 per thread,
// 8-row segments.  128 threads cover D=512.
// ---------------------------------------------------------------------------
__device__ __forceinline__ float fast_tanh(float x)
{
    float e = __expf(2.f * x);
    return 1.f - __fdividef(2.f, 1.f + e);
}

__global__ __launch_bounds__(128) void conv_kernel(
    const float* __restrict__ F0r, const float* __restrict__ F1r,
    const float* __restrict__ m0, const float* __restrict__ m1,
    const float* __restrict__ conv_w, const float* __restrict__ conv_b,
    float* __restrict__ out)
{
    const int p = blockIdx.z & 1;
    const int b = blockIdx.z >> 1;
    const float* F  = p ? F1r : F0r;
    const float* mk = p ? m1 : m0;
    const float* Fa = p ? g_F1a : g_F0a;
    float* o = out + ((size_t)p * BB + b) * SS * DD;

    const int s0 = blockIdx.y * 8;
    const int d  = threadIdx.x * 4;

    float w0[3], w1[3];
    #pragma unroll
    for (int h = 0; h < 3; h++) { w0[h] = conv_w[h]; w1[h] = conv_w[3 + h]; }
    const float cb = conv_b[0];

    float4 xf[12], xa[12];
    #pragma unroll
    for (int u = 0; u < 12; u++) {
        int t = s0 - 2 + u;
        bool in = (t >= 0) && (t < SS);
        if (in) {
            float mv = mk[b * SS + t];
            float4 f = *(const float4*)&F[((size_t)b * SS + t) * DD + d];
            xf[u] = make_float4(f.x * mv, f.y * mv, f.z * mv, f.w * mv);
            xa[u] = *(const float4*)&Fa[((size_t)b * SS + t) * DD + d];
        } else {
            xf[u] = make_float4(0.f, 0.f, 0.f, 0.f);
            xa[u] = make_float4(0.f, 0.f, 0.f, 0.f);
        }
    }

    float4 y[10];
    #pragma unroll
    for (int u = 0; u < 10; u++) {
        float ax = cb, ay = cb, az = cb, aw = cb;
        #pragma unroll
        for (int h = 0; h < 3; h++) {
            ax += w0[h] * xf[u + h].x + w1[h] * xa[u + h].x;
            ay += w0[h] * xf[u + h].y + w1[h] * xa[u + h].y;
            az += w0[h] * xf[u + h].z + w1[h] * xa[u + h].z;
            aw += w0[h] * xf[u + h].w + w1[h] * xa[u + h].w;
        }
        y[u] = make_float4(fast_tanh(ax), fast_tanh(ay), fast_tanh(az), fast_tanh(aw));
    }
    #pragma unroll
    for (int q = 0; q < 8; q++) {
        float4 r = make_float4(
            (y[q].x + y[q + 1].x + y[q + 2].x) * (1.f / 3.f),
            (y[q].y + y[q + 1].y + y[q + 2].y) * (1.f / 3.f),
            (y[q].z + y[q + 1].z + y[q + 2].z) * (1.f / 3.f),
            (y[q].w + y[q + 1].w + y[q + 2].w) * (1.f / 3.f));
        *(float4*)&o[(size_t)(s0 + q) * DD + d] = r;
    }
}

// ---------------------------------------------------------------------------
// Launch
// ---------------------------------------------------------------------------
extern "C" void kernel_launch(void* const* d_in, const int* in_sizes, int n_in,
                              void* d_out, int out_size)
{
    const float* F0r    = (const float*)d_in[0];
    const float* F1r    = (const float*)d_in[1];
    const float* m0     = (const float*)d_in[2];
    const float* m1     = (const float*)d_in[3];
    const float* W0     = (const float*)d_in[4];
    const float* W1     = (const float*)d_in[5];
    const float* conv_w = (const float*)d_in[6];
    const float* conv_b = (const float*)d_in[7];
    float* out = (float*)d_out;

    cudaFuncSetAttribute(gemm_attn, cudaFuncAttributeMaxDynamicSharedMemorySize, GEMM_SMEM);
    cudaFuncSetAttribute(gemm_aggr, cudaFuncAttributeMaxDynamicSharedMemorySize, GEMM_SMEM);

    prep_kernel<<<8448, 256>>>(F0r, F1r, m0, m1, W0, W1);

    gemm_attn<<<dim3(2, 2, BB), 256, GEMM_SMEM>>>(F0r, F1r, m0, m1);
    gemm_aggr<<<dim3(4, 4, BB), 256, GEMM_SMEM>>>();

    conv_kernel<<<dim3(1, 32, 2 * BB), 128>>>(F0r, F1r, m0, m1, conv_w, conv_b, out);
}

// round 8
// speedup vs baseline: 1.3012x; 1.3012x over previous
#include <cuda_runtime.h>
#include <cstdint>
#include <math.h>

#define BB 64
#define SS 256
#define DD 512

// ---------------- scratch (__device__ globals; no allocation) ---------------
__device__ float g_A  [BB * SS * SS];    // A[b][i][j]   (tf32-rounded)
__device__ float g_At [BB * SS * SS];    // A[b][j][i]   (tf32-rounded)
__device__ float g_F0a[BB * SS * DD];
__device__ float g_F1a[BB * SS * DD];
__device__ float g_W0t[DD * SS];         // W0^T [d][k]  (tf32-rounded)
__device__ float g_W1t[DD * SS];
__device__ float g_sq0[BB * SS];
__device__ float g_sq1[BB * SS];

// ---------------- helpers ---------------------------------------------------
__device__ __forceinline__ uint32_t smem_u32(const void* p) {
    uint32_t a;
    asm("{ .reg .u64 t; cvta.to.shared.u64 t, %1; cvt.u32.u64 %0, t; }" : "=r"(a) : "l"(p));
    return a;
}
__device__ __forceinline__ float rtf32(float x) {   // round-to-nearest tf32
    uint32_t u;
    asm("cvt.rna.tf32.f32 %0, %1;" : "=r"(u) : "f"(x));
    return __uint_as_float(u);
}
__device__ __forceinline__ uint32_t lds32(uint32_t a) {
    uint32_t v;
    asm volatile("ld.shared.b32 %0, [%1];" : "=r"(v) : "r"(a));
    return v;
}
#define CP_ASYNC16(dst, src) \
    asm volatile("cp.async.cg.shared.global [%0], [%1], 16;" :: "r"(dst), "l"(src))
#define CP_COMMIT() asm volatile("cp.async.commit_group;" ::: "memory")
#define CP_WAIT1()  asm volatile("cp.async.wait_group 1;" ::: "memory")

__device__ __forceinline__ void mma_tf32(float* c, const uint32_t* a, const uint32_t* b) {
    asm volatile(
        "mma.sync.aligned.m16n8k8.row.col.f32.tf32.tf32.f32 "
        "{%0,%1,%2,%3}, {%4,%5,%6,%7}, {%8,%9}, {%0,%1,%2,%3};"
        : "+f"(c[0]), "+f"(c[1]), "+f"(c[2]), "+f"(c[3])
        : "r"(a[0]), "r"(a[1]), "r"(a[2]), "r"(a[3]), "r"(b[0]), "r"(b[1]));
}

// ---------------------------------------------------------------------------
// Prep kernel: sqnorms (blocks 0..8191, 2 rows each) + W transpose (8192..8447)
// ---------------------------------------------------------------------------
__global__ __launch_bounds__(256) void prep_kernel(
    const float* __restrict__ F0r, const float* __restrict__ F1r,
    const float* __restrict__ m0, const float* __restrict__ m1,
    const float* __restrict__ W0, const float* __restrict__ W1)
{
    __shared__ float sh0[2][4], sh1[2][4];
    __shared__ float t[32][33];
    int bx = blockIdx.x;
    int tid = threadIdx.x;

    if (bx < 8192) {
        int half = tid >> 7, lt = tid & 127;
        int row = bx * 2 + half;
        const float4* r0 = (const float4*)(F0r + (size_t)row * DD);
        const float4* r1 = (const float4*)(F1r + (size_t)row * DD);
        float4 a = r0[lt];
        float4 b = r1[lt];
        float s0 = a.x * a.x + a.y * a.y + a.z * a.z + a.w * a.w;
        float s1 = b.x * b.x + b.y * b.y + b.z * b.z + b.w * b.w;
        #pragma unroll
        for (int o = 16; o > 0; o >>= 1) {
            s0 += __shfl_xor_sync(0xFFFFFFFFu, s0, o);
            s1 += __shfl_xor_sync(0xFFFFFFFFu, s1, o);
        }
        int w = lt >> 5;
        if ((lt & 31) == 0) { sh0[half][w] = s0; sh1[half][w] = s1; }
        __syncthreads();
        if (lt == 0) {
            s0 = sh0[half][0] + sh0[half][1] + sh0[half][2] + sh0[half][3];
            s1 = sh1[half][0] + sh1[half][1] + sh1[half][2] + sh1[half][3];
            g_sq0[row] = s0 * m0[row];
            g_sq1[row] = s1 * m1[row];
        }
    } else {
        int r = bx - 8192;                 // 0..255
        int sel = r >> 7;
        int d0 = (r & 15) * 32;
        int k0 = ((r >> 4) & 7) * 32;
        const float* W = sel ? W1 : W0;
        float* Wt = sel ? g_W1t : g_W0t;
        int tx = tid & 31, ty = tid >> 5;  // 32 x 8
        #pragma unroll
        for (int rr = 0; rr < 32; rr += 8)
            t[ty + rr][tx] = W[(size_t)(k0 + ty + rr) * DD + d0 + tx];
        __syncthreads();
        #pragma unroll
        for (int rr = 0; rr < 32; rr += 8)
            Wt[(size_t)(d0 + ty + rr) * SS + k0 + tx] = rtf32(t[tx][ty + rr]);
    }
}

// ---------------------------------------------------------------------------
// mma.sync tf32 GEMM core.  Block tile 128x128, 512 threads, 16 warps in a
// 4x4 grid, warp tile 32x32.  BK=16, smem rows of 16+4 floats (80 B,
// conflict-free).  3-stage cp.async ring, one __syncthreads per k-tile,
// loads issued 2 tiles ahead.
// ---------------------------------------------------------------------------
#define OPER_BYTES (128 * 80)              // 10240
#define STAGE_BYTES (2 * OPER_BYTES)       // 20480
#define NSTAGE 3
#define GEMM_SMEM (NSTAGE * STAGE_BYTES)   // 61440

template <int KTOT>
__device__ __forceinline__ void gemm_mainloop(
    const float* __restrict__ Ag, const float* __restrict__ Bg,
    uint32_t sb, int tid, float acc[2][4][4],
    uint32_t aoff, uint32_t boff)
{
    constexpr int T = KTOT / 16;
    const int lrow = tid >> 2;             // 0..127
    const int lpart = tid & 3;             // 16B part

    auto load_tile = [&](int t, int s) {
        uint32_t ab = sb + s * STAGE_BYTES;
        uint32_t bb = ab + OPER_BYTES;
        int k0 = t * 16;
        uint32_t doff = (uint32_t)(lrow * 80 + lpart * 16);
        CP_ASYNC16(ab + doff, Ag + (size_t)lrow * KTOT + k0 + lpart * 4);
        CP_ASYNC16(bb + doff, Bg + (size_t)lrow * KTOT + k0 + lpart * 4);
    };

    load_tile(0, 0); CP_COMMIT();
    load_tile(1, 1); CP_COMMIT();

    int s = 0;
    for (int t = 0; t < T; t++) {
        CP_WAIT1();           // tile t resident (t+1 may be in flight)
        __syncthreads();      // visibility; slot s+2 reusable
        int lt = t + 2;
        int ls = s + 2; if (ls >= NSTAGE) ls -= NSTAGE;
        if (lt < T) load_tile(lt, ls);
        CP_COMMIT();

        uint32_t ab = sb + s * STAGE_BYTES + aoff;
        uint32_t bb = sb + s * STAGE_BYTES + OPER_BYTES + boff;
        #pragma unroll
        for (int ks = 0; ks < 2; ks++) {
            uint32_t af[2][4], bf[4][2];
            #pragma unroll
            for (int mf = 0; mf < 2; mf++) {
                uint32_t base = ab + mf * (16 * 80) + ks * 32;
                af[mf][0] = lds32(base);
                af[mf][1] = lds32(base + 8 * 80);
                af[mf][2] = lds32(base + 16);
                af[mf][3] = lds32(base + 8 * 80 + 16);
            }
            #pragma unroll
            for (int nf = 0; nf < 4; nf++) {
                uint32_t base = bb + nf * (8 * 80) + ks * 32;
                bf[nf][0] = lds32(base);
                bf[nf][1] = lds32(base + 16);
            }
            #pragma unroll
            for (int mf = 0; mf < 2; mf++)
                #pragma unroll
                for (int nf = 0; nf < 4; nf++)
                    mma_tf32(acc[mf][nf], af[mf], bf[nf]);
        }
        if (++s >= NSTAGE) s -= NSTAGE;
    }
}

// ---------------------------------------------------------------------------
// GEMM A (attention): cross = F0 @ F1^T (K=512) -> epilogue -> g_A, g_At
// ---------------------------------------------------------------------------
__global__ __launch_bounds__(512, 2) void gemm_attn(
    const float* __restrict__ F0r, const float* __restrict__ F1r,
    const float* __restrict__ m0_, const float* __restrict__ m1_)
{
    extern __shared__ char smem[];
    const int tid = threadIdx.x;
    const int wid = tid >> 5, lane = tid & 31;
    const int g = lane >> 2, t4 = lane & 3;
    const int wm = wid & 3, wn = wid >> 2;     // 4 x 4 warp grid
    const int b = blockIdx.z, mt = blockIdx.y, nt = blockIdx.x;

    uint32_t sb = smem_u32(smem);
    const float* Ag = F0r + (size_t)b * SS * DD + (size_t)mt * 128 * DD;
    const float* Bg = F1r + (size_t)b * SS * DD + (size_t)nt * 128 * DD;

    float acc[2][4][4];
    #pragma unroll
    for (int i = 0; i < 2; i++)
        #pragma unroll
        for (int j = 0; j < 4; j++)
            #pragma unroll
            for (int r = 0; r < 4; r++) acc[i][j][r] = 0.f;

    const uint32_t aoff = (uint32_t)((wm * 32 + g) * 80 + t4 * 4);
    const uint32_t boff = (uint32_t)((wn * 32 + g) * 80 + t4 * 4);

    gemm_mainloop<512>(Ag, Bg, sb, tid, acc, aoff, boff);

    // -------------------- attention epilogue (two 64-row halves) ------------
    float* tile = (float*)smem;                         // [64][132]
    float* s_sq0 = (float*)(smem + 33792);              // [128]
    float* s_a0  = s_sq0 + 128;
    float* s_sq1 = s_a0 + 128;
    float* s_m1  = s_sq1 + 128;

    __syncthreads();   // mainloop smem dead
    if (tid < 128) {
        int i = tid;
        s_sq0[i] = g_sq0[b * SS + mt * 128 + i];
        s_a0[i]  = 2.f * m0_[b * SS + mt * 128 + i];
        s_sq1[i] = g_sq1[b * SS + nt * 128 + i];
        s_m1[i]  = m1_[b * SS + nt * 128 + i];
    }

    float* Aout  = g_A  + (size_t)b * SS * SS;
    float* Atout = g_At + (size_t)b * SS * SS;

    #pragma unroll 1
    for (int h = 0; h < 2; h++) {
        __syncthreads();
        if ((wm >> 1) == h) {
            #pragma unroll
            for (int mf = 0; mf < 2; mf++) {
                int lr = (wm & 1) * 32 + mf * 16 + g;
                #pragma unroll
                for (int nf = 0; nf < 4; nf++) {
                    int col = wn * 32 + nf * 8 + 2 * t4;
                    *(float2*)&tile[lr * 132 + col] =
                        make_float2(acc[mf][nf][0], acc[mf][nf][1]);
                    *(float2*)&tile[(lr + 8) * 132 + col] =
                        make_float2(acc[mf][nf][2], acc[mf][nf][3]);
                }
            }
        }
        __syncthreads();

        #pragma unroll
        for (int it = 0; it < 4; it++) {
            int lin = it * 2048 + tid * 4;
            int row = lin >> 7, col = lin & 127;
            int grow = h * 64 + row;
            float s0v = s_sq0[grow], a0v = s_a0[grow];
            float4 cr = *(float4*)&tile[row * 132 + col];
            float d2, v0, v1, v2, v3;
            d2 = fmaxf(s0v + s_sq1[col]     - a0v * s_m1[col]     * cr.x, 0.f);
            v0 = rtf32(1.f / (1.f + sqrtf(d2)));
            d2 = fmaxf(s0v + s_sq1[col + 1] - a0v * s_m1[col + 1] * cr.y, 0.f);
            v1 = rtf32(1.f / (1.f + sqrtf(d2)));
            d2 = fmaxf(s0v + s_sq1[col + 2] - a0v * s_m1[col + 2] * cr.z, 0.f);
            v2 = rtf32(1.f / (1.f + sqrtf(d2)));
            d2 = fmaxf(s0v + s_sq1[col + 3] - a0v * s_m1[col + 3] * cr.w, 0.f);
            v3 = rtf32(1.f / (1.f + sqrtf(d2)));
            *(float4*)&Aout[(size_t)(mt * 128 + grow) * SS + nt * 128 + col] =
                make_float4(v0, v1, v2, v3);
        }

        #pragma unroll
        for (int it = 0; it < 4; it++) {
            int pair = it * 512 + tid;
            int col = pair >> 4, rg = pair & 15;
            int r0 = rg * 4;
            float s1v = s_sq1[col], m1v = s_m1[col];
            float v[4];
            #pragma unroll
            for (int q = 0; q < 4; q++) {
                int row = r0 + q, grow = h * 64 + row;
                float cr = tile[row * 132 + col];
                float d2 = fmaxf(s_sq0[grow] + s1v - s_a0[grow] * m1v * cr, 0.f);
                v[q] = rtf32(1.f / (1.f + sqrtf(d2)));
            }
            *(float4*)&Atout[(size_t)(nt * 128 + col) * SS + mt * 128 + h * 64 + r0] =
                make_float4(v[0], v[1], v[2], v[3]);
        }
    }
}

// ---------------------------------------------------------------------------
// GEMM B (both aggregations in ONE launch).  blockIdx.y: 0,1 -> F0a (At@W0t),
// 2,3 -> F1a (A@W1t).  K=256.
// ---------------------------------------------------------------------------
__global__ __launch_bounds__(512, 2) void gemm_aggr(void)
{
    extern __shared__ char smem[];
    const int tid = threadIdx.x;
    const int wid = tid >> 5, lane = tid & 31;
    const int g = lane >> 2, t4 = lane & 3;
    const int wm = wid & 3, wn = wid >> 2;
    const int b = blockIdx.z, nt = blockIdx.x;
    const int sel = blockIdx.y >> 1;          // 0: F0a, 1: F1a
    const int mt  = blockIdx.y & 1;

    uint32_t sb = smem_u32(smem);
    const float* Ag = (sel ? g_A : g_At) + (size_t)b * SS * SS + (size_t)mt * 128 * SS;
    const float* Bg = (sel ? g_W1t : g_W0t) + (size_t)nt * 128 * SS;

    float acc[2][4][4];
    #pragma unroll
    for (int i = 0; i < 2; i++)
        #pragma unroll
        for (int j = 0; j < 4; j++)
            #pragma unroll
            for (int r = 0; r < 4; r++) acc[i][j][r] = 0.f;

    const uint32_t aoff = (uint32_t)((wm * 32 + g) * 80 + t4 * 4);
    const uint32_t boff = (uint32_t)((wn * 32 + g) * 80 + t4 * 4);

    gemm_mainloop<256>(Ag, Bg, sb, tid, acc, aoff, boff);

    float* O = (sel ? g_F1a : g_F0a) + (size_t)b * SS * DD;
    #pragma unroll
    for (int mf = 0; mf < 2; mf++) {
        int m = mt * 128 + wm * 32 + mf * 16 + g;
        #pragma unroll
        for (int nf = 0; nf < 4; nf++) {
            int col = nt * 128 + wn * 32 + nf * 8 + 2 * t4;
            *(float2*)&O[(size_t)m * DD + col] =
                make_float2(acc[mf][nf][0], acc[mf][nf][1]);
            *(float2*)&O[(size_t)(m + 8) * DD + col] =
                make_float2(acc[mf][nf][2], acc[mf][nf][3]);
        }
    }
}

// ---------------------------------------------------------------------------
// Conv (2ch, h=3, pad 2) + bias + tanh + avgpool(3), float2 per thread,
// 8-row segments.  256 threads cover D=512.
// ---------------------------------------------------------------------------
__device__ __forceinline__ float fast_tanh(float x)
{
    float e = __expf(2.f * x);
    return 1.f - __fdividef(2.f, 1.f + e);
}

__global__ __launch_bounds__(256) void conv_kernel(
    const float* __restrict__ F0r, const float* __restrict__ F1r,
    const float* __restrict__ m0, const float* __restrict__ m1,
    const float* __restrict__ conv_w, const float* __restrict__ conv_b,
    float* __restrict__ out)
{
    const int p = blockIdx.y & 1;
    const int b = blockIdx.y >> 1;
    const float* F  = p ? F1r : F0r;
    const float* mk = p ? m1 : m0;
    const float* Fa = p ? g_F1a : g_F0a;
    float* o = out + ((size_t)p * BB + b) * SS * DD;

    const int s0 = blockIdx.x * 8;
    const int d  = threadIdx.x * 2;

    float w0[3], w1[3];
    #pragma unroll
    for (int h = 0; h < 3; h++) { w0[h] = conv_w[h]; w1[h] = conv_w[3 + h]; }
    const float cb = conv_b[0];

    float2 xf[12], xa[12];
    #pragma unroll
    for (int u = 0; u < 12; u++) {
        int t = s0 - 2 + u;
        bool in = (t >= 0) && (t < SS);
        if (in) {
            float mv = mk[b * SS + t];
            float2 f = *(const float2*)&F[((size_t)b * SS + t) * DD + d];
            xf[u] = make_float2(f.x * mv, f.y * mv);
            xa[u] = *(const float2*)&Fa[((size_t)b * SS + t) * DD + d];
        } else {
            xf[u] = make_float2(0.f, 0.f);
            xa[u] = make_float2(0.f, 0.f);
        }
    }

    float2 y[10];
    #pragma unroll
    for (int u = 0; u < 10; u++) {
        float ax = cb, ay = cb;
        #pragma unroll
        for (int h = 0; h < 3; h++) {
            ax += w0[h] * xf[u + h].x + w1[h] * xa[u + h].x;
            ay += w0[h] * xf[u + h].y + w1[h] * xa[u + h].y;
        }
        y[u] = make_float2(fast_tanh(ax), fast_tanh(ay));
    }
    #pragma unroll
    for (int q = 0; q < 8; q++) {
        float2 r = make_float2(
            (y[q].x + y[q + 1].x + y[q + 2].x) * (1.f / 3.f),
            (y[q].y + y[q + 1].y + y[q + 2].y) * (1.f / 3.f));
        *(float2*)&o[(size_t)(s0 + q) * DD + d] = r;
    }
}

// ---------------------------------------------------------------------------
// Launch
// ---------------------------------------------------------------------------
extern "C" void kernel_launch(void* const* d_in, const int* in_sizes, int n_in,
                              void* d_out, int out_size)
{
    const float* F0r    = (const float*)d_in[0];
    const float* F1r    = (const float*)d_in[1];
    const float* m0     = (const float*)d_in[2];
    const float* m1     = (const float*)d_in[3];
    const float* W0     = (const float*)d_in[4];
    const float* W1     = (const float*)d_in[5];
    const float* conv_w = (const float*)d_in[6];
    const float* conv_b = (const float*)d_in[7];
    float* out = (float*)d_out;

    cudaFuncSetAttribute(gemm_attn, cudaFuncAttributeMaxDynamicSharedMemorySize, GEMM_SMEM);
    cudaFuncSetAttribute(gemm_aggr, cudaFuncAttributeMaxDynamicSharedMemorySize, GEMM_SMEM);

    prep_kernel<<<8448, 256>>>(F0r, F1r, m0, m1, W0, W1);

    gemm_attn<<<dim3(2, 2, BB), 512, GEMM_SMEM>>>(F0r, F1r, m0, m1);
    gemm_aggr<<<dim3(4, 4, BB), 512, GEMM_SMEM>>>();

    conv_kernel<<<dim3(32, 2 * BB), 256>>>(F0r, F1r, m0, m1, conv_w, conv_b, out);
}